// round 1
// baseline (speedup 1.0000x reference)
#include <cuda_runtime.h>
#include <math.h>

#define NSLOPE 0.2f
#define NN 1024
#define F 128

// scratch (device globals: allocation-free)
__device__ float g_X[NN * F];
__device__ float g_Y[NN * F];
__device__ float g_H[NN * F];
__device__ float g_asf[NN];
__device__ float g_adf[NN];

__device__ __forceinline__ float lrelu(float x) { return x > 0.f ? x : NSLOPE * x; }

// ---------------------------------------------------------------------------
// concat desc1|desc2 -> X0
__global__ void concat_kernel(const float* __restrict__ d1, const float* __restrict__ d2,
                              float* __restrict__ X) {
    int i = blockIdx.x * blockDim.x + threadIdx.x;
    X[i] = (i < 512 * F) ? d1[i] : d2[i - 512 * F];
}

// ---------------------------------------------------------------------------
// H[n][j] = sum_k X[n][k] * W[k][j]; 8 rows per block, 128 threads (one col each)
__global__ void gemm8(const float* __restrict__ X, const float* __restrict__ W,
                      float* __restrict__ H) {
    __shared__ float xs[8][F];
    int n0 = blockIdx.x * 8;
    int tid = threadIdx.x;
#pragma unroll
    for (int i = 0; i < 8; i++)
        ((float*)xs)[tid + i * 128] = X[n0 * F + tid + i * 128];
    __syncthreads();
    float acc[8] = {0.f, 0.f, 0.f, 0.f, 0.f, 0.f, 0.f, 0.f};
#pragma unroll 4
    for (int k = 0; k < F; k++) {
        float w = W[k * F + tid];
#pragma unroll
        for (int r = 0; r < 8; r++) acc[r] = fmaf(xs[r][k], w, acc[r]);
    }
#pragma unroll
    for (int r = 0; r < 8; r++) H[(n0 + r) * F + tid] = acc[r];
}

// ---------------------------------------------------------------------------
// Multi-head (H=128, C=1) GAT attention over dense group edges + ELU.
// grid (128 heads, 2 dst groups), block 128 threads, 4 dsts/thread.
// Factorized softmax: per-src P1=exp(as-M), P2=exp(0.2(as-M)); per (d,s) pair
// only a compare + predicated adds. Shift C = lrelu(max score) keeps all
// exponents <= 0 (same stability as reference softmax).
template <bool CROSS>
__global__ void attn128(const float* __restrict__ H, const float* __restrict__ a_src,
                        const float* __restrict__ a_dst, const float* __restrict__ bias,
                        float* __restrict__ Xout) {
    int h = blockIdx.x;
    int dg = blockIdx.y;
    int sg = CROSS ? (1 - dg) : dg;
    __shared__ float sAs[512];
    __shared__ float2 sB1[512];  // (P1, P1*v)
    __shared__ float2 sB2[512];  // (P2, P2*v)
    __shared__ float sred[4];
    int tid = threadIdx.x;
    float asrc = a_src[h], adst = a_dst[h];

    // load src column of H, compute as = H*asrc
    float lv[4], la[4];
#pragma unroll
    for (int i = 0; i < 4; i++) {
        int s = tid + i * 128;
        float Hv = H[(sg * 512 + s) * F + h];
        lv[i] = Hv;
        la[i] = Hv * asrc;
    }
    // block max of as
    float m = fmaxf(fmaxf(la[0], la[1]), fmaxf(la[2], la[3]));
#pragma unroll
    for (int o = 16; o; o >>= 1) m = fmaxf(m, __shfl_xor_sync(0xffffffffu, m, o));
    if ((tid & 31) == 0) sred[tid >> 5] = m;
    __syncthreads();
    float M = fmaxf(fmaxf(sred[0], sred[1]), fmaxf(sred[2], sred[3]));

#pragma unroll
    for (int i = 0; i < 4; i++) {
        int s = tid + i * 128;
        float p1 = __expf(la[i] - M);
        float p2 = __expf(NSLOPE * (la[i] - M));
        sAs[s] = la[i];
        sB1[s] = make_float2(p1, p1 * lv[i]);
        sB2[s] = make_float2(p2, p2 * lv[i]);
    }

    // dst-side values
    float Hd[4], adv[4], negad[4];
#pragma unroll
    for (int i = 0; i < 4; i++) {
        int dn = dg * 512 + tid + i * 128;
        float v = H[dn * F + h];
        Hd[i] = v;
        adv[i] = v * adst;
        negad[i] = -adv[i];
    }
    __syncthreads();

    float acc1[4] = {0, 0, 0, 0}, acc1v[4] = {0, 0, 0, 0};
    float acc2[4] = {0, 0, 0, 0}, acc2v[4] = {0, 0, 0, 0};
#pragma unroll 4
    for (int s = 0; s < 512; s++) {
        float a = sAs[s];
        float2 b1 = sB1[s];
        float2 b2 = sB2[s];
#pragma unroll
        for (int i = 0; i < 4; i++) {
            bool c = a > negad[i];
            acc1[i] += c ? b1.x : 0.f;
            acc1v[i] += c ? b1.y : 0.f;
            acc2[i] += c ? 0.f : b2.x;
            acc2v[i] += c ? 0.f : b2.y;
        }
    }

    float bh = bias[h];
#pragma unroll
    for (int i = 0; i < 4; i++) {
        int dn = dg * 512 + tid + i * 128;
        float ad = adv[i];
        float T = M + ad;  // max pre-activation score over src group
        float tmax = T, ts = 0.f;
        if (CROSS) {
            ts = Hd[i] * asrc + ad;  // self-loop score
            tmax = fmaxf(tmax, ts);
        }
        float C = lrelu(tmax);
        float f1 = __expf(T - C);
        float f2 = __expf(NSLOPE * T - C);
        float num = f1 * acc1v[i] + f2 * acc2v[i];
        float den = f1 * acc1[i] + f2 * acc2[i];
        if (CROSS) {
            float ws = __expf(lrelu(ts) - C);
            num = fmaf(ws, Hd[i], num);
            den += ws;
        }
        float o = num / (den + 1e-16f) + bh;
        o = o > 0.f ? o : expm1f(o);  // ELU
        Xout[dn * F + h] = o;
    }
}

// ---------------------------------------------------------------------------
// final layer (heads=1, out_ch=128): per-node attention logits
__global__ void dots_kernel(const float* __restrict__ H, const float* __restrict__ a_s,
                            const float* __restrict__ a_d, float* __restrict__ asf,
                            float* __restrict__ adf) {
    int n = blockIdx.x, t = threadIdx.x;
    float h = H[n * F + t];
    float s1 = h * a_s[t];
    float s2 = h * a_d[t];
#pragma unroll
    for (int o = 16; o; o >>= 1) {
        s1 += __shfl_xor_sync(0xffffffffu, s1, o);
        s2 += __shfl_xor_sync(0xffffffffu, s2, o);
    }
    __shared__ float r1[4], r2[4];
    if ((t & 31) == 0) { r1[t >> 5] = s1; r2[t >> 5] = s2; }
    __syncthreads();
    if (t == 0) {
        asf[n] = r1[0] + r1[1] + r1[2] + r1[3];
        adf[n] = r2[0] + r2[1] + r2[2] + r2[3];
    }
}

// final cross-attention: 8 dsts per block (shares src H rows), 128 threads = channels
__global__ void final_attn(const float* __restrict__ H, const float* __restrict__ asf,
                           const float* __restrict__ adf, const float* __restrict__ bias,
                           float* __restrict__ out) {
    int d0 = blockIdx.x * 8;
    int dg = d0 >> 9;
    int sg = 1 - dg;
    int tid = threadIdx.x;
    __shared__ float sAsf[512];
    __shared__ float sw[8][512];
    __shared__ float sAdf[8], sM[8], sSelf[8];
    __shared__ float sred[4];

    float mloc = -1e30f;
#pragma unroll
    for (int i = 0; i < 4; i++) {
        int s = tid + i * 128;
        float v = asf[sg * 512 + s];
        sAsf[s] = v;
        mloc = fmaxf(mloc, v);
    }
#pragma unroll
    for (int o = 16; o; o >>= 1) mloc = fmaxf(mloc, __shfl_xor_sync(0xffffffffu, mloc, o));
    if ((tid & 31) == 0) sred[tid >> 5] = mloc;
    __syncthreads();
    float maxasf = fmaxf(fmaxf(sred[0], sred[1]), fmaxf(sred[2], sred[3]));

    if (tid < 8) {
        int dn = d0 + tid;
        float ad = adf[dn];
        float ts = asf[dn] + ad;
        float tmax = fmaxf(maxasf + ad, ts);
        float mm = lrelu(tmax);
        sAdf[tid] = ad;
        sM[tid] = mm;
        sSelf[tid] = __expf(lrelu(ts) - mm);
    }
    __syncthreads();

    for (int s = tid; s < 512; s += 128) {
        float a = sAsf[s];
#pragma unroll
        for (int d = 0; d < 8; d++)
            sw[d][s] = __expf(lrelu(a + sAdf[d]) - sM[d]);
    }
    __syncthreads();

    float acc[8] = {0, 0, 0, 0, 0, 0, 0, 0};
    float den[8] = {0, 0, 0, 0, 0, 0, 0, 0};
    const float* Hs = H + sg * 512 * F + tid;
#pragma unroll 2
    for (int s = 0; s < 512; s++) {
        float hv = Hs[s * F];
#pragma unroll
        for (int d = 0; d < 8; d++) {
            float w = sw[d][s];
            acc[d] = fmaf(w, hv, acc[d]);
            den[d] += w;
        }
    }
    float bc = bias[tid];
#pragma unroll
    for (int d = 0; d < 8; d++) {
        int dn = d0 + d;
        float hvd = H[dn * F + tid];
        float ws = sSelf[d];
        float o = fmaf(ws, hvd, acc[d]) / (den[d] + ws + 1e-16f);
        out[dn * F + tid] = o + bc;
    }
}

// ---------------------------------------------------------------------------
extern "C" void kernel_launch(void* const* d_in, const int* in_sizes, int n_in,
                              void* d_out, int out_size) {
    const float* desc1 = (const float*)d_in[0];
    const float* desc2 = (const float*)d_in[1];
    const float* W1 = (const float*)d_in[2];
    const float* as1 = (const float*)d_in[3];
    const float* ad1 = (const float*)d_in[4];
    const float* b1 = (const float*)d_in[5];
    const float* W2 = (const float*)d_in[6];
    const float* as2 = (const float*)d_in[7];
    const float* ad2 = (const float*)d_in[8];
    const float* b2 = (const float*)d_in[9];
    float* out = (float*)d_out;

    float *X, *Y, *H, *asf, *adf;
    cudaGetSymbolAddress((void**)&X, g_X);
    cudaGetSymbolAddress((void**)&Y, g_Y);
    cudaGetSymbolAddress((void**)&H, g_H);
    cudaGetSymbolAddress((void**)&asf, g_asf);
    cudaGetSymbolAddress((void**)&adf, g_adf);

    concat_kernel<<<256, 512>>>(desc1, desc2, X);

    dim3 ag(128, 2);
    // conv1: inside
    gemm8<<<128, 128>>>(X, W1, H);
    attn128<false><<<ag, 128>>>(H, as1, ad1, b1, Y);
    // conv2: cross
    gemm8<<<128, 128>>>(Y, W1, H);
    attn128<true><<<ag, 128>>>(H, as1, ad1, b1, X);
    // conv3: inside
    gemm8<<<128, 128>>>(X, W1, H);
    attn128<false><<<ag, 128>>>(H, as1, ad1, b1, Y);
    // conv4: cross
    gemm8<<<128, 128>>>(Y, W1, H);
    attn128<true><<<ag, 128>>>(H, as1, ad1, b1, X);
    // final conv: cross, heads=1, out_ch=128, no ELU
    gemm8<<<128, 128>>>(X, W2, H);
    dots_kernel<<<1024, 128>>>(H, as2, ad2, asf, adf);
    final_attn<<<128, 128>>>(H, asf, adf, b2, out);
}

// round 2
// speedup vs baseline: 1.6969x; 1.6969x over previous
#include <cuda_runtime.h>
#include <math.h>

#define NSLOPE 0.2f
#define NN 1024
#define F 128

// scratch (device globals: allocation-free)
__device__ float g_X[NN * F];
__device__ float g_Y[NN * F];
__device__ float g_H[NN * F];
__device__ float g_asf[NN];
__device__ float g_adf[NN];

__device__ __forceinline__ float lrelu(float x) { return x > 0.f ? x : NSLOPE * x; }

// ---------------------------------------------------------------------------
// concat desc1|desc2 -> X0
__global__ void concat_kernel(const float* __restrict__ d1, const float* __restrict__ d2,
                              float* __restrict__ X) {
    int i = blockIdx.x * blockDim.x + threadIdx.x;
    X[i] = (i < 512 * F) ? d1[i] : d2[i - 512 * F];
}

// ---------------------------------------------------------------------------
// GEMM: H = X @ W.  grid 256 (4 rows/block), block 256 (128 cols x 2 k-halves).
__global__ void gemm4(const float* __restrict__ X, const float* __restrict__ W,
                      float* __restrict__ H) {
    __shared__ float xs[4][F];
    __shared__ float pr[4][F];
    int tid = threadIdx.x;
    int col = tid & 127;
    int ks = tid >> 7;  // 0 or 1
    int n0 = blockIdx.x * 4;
    ((float*)xs)[tid] = X[n0 * F + tid];
    ((float*)xs)[tid + 256] = X[n0 * F + tid + 256];
    __syncthreads();

    float a0 = 0.f, a1 = 0.f, a2 = 0.f, a3 = 0.f;
    const float* Wp = W + (ks * 64) * F + col;
    const float4* x40 = reinterpret_cast<const float4*>(&xs[0][0]) + ks * 16;
    const float4* x41 = reinterpret_cast<const float4*>(&xs[1][0]) + ks * 16;
    const float4* x42 = reinterpret_cast<const float4*>(&xs[2][0]) + ks * 16;
    const float4* x43 = reinterpret_cast<const float4*>(&xs[3][0]) + ks * 16;
#pragma unroll 4
    for (int kq = 0; kq < 16; kq++) {
        float w0 = Wp[(kq * 4 + 0) * F];
        float w1 = Wp[(kq * 4 + 1) * F];
        float w2 = Wp[(kq * 4 + 2) * F];
        float w3 = Wp[(kq * 4 + 3) * F];
        float4 x0 = x40[kq], x1 = x41[kq], x2 = x42[kq], x3 = x43[kq];
        a0 = fmaf(x0.x, w0, fmaf(x0.y, w1, fmaf(x0.z, w2, fmaf(x0.w, w3, a0))));
        a1 = fmaf(x1.x, w0, fmaf(x1.y, w1, fmaf(x1.z, w2, fmaf(x1.w, w3, a1))));
        a2 = fmaf(x2.x, w0, fmaf(x2.y, w1, fmaf(x2.z, w2, fmaf(x2.w, w3, a2))));
        a3 = fmaf(x3.x, w0, fmaf(x3.y, w1, fmaf(x3.z, w2, fmaf(x3.w, w3, a3))));
    }
    if (ks) {
        pr[0][col] = a0; pr[1][col] = a1; pr[2][col] = a2; pr[3][col] = a3;
    }
    __syncthreads();
    if (!ks) {
        H[(n0 + 0) * F + col] = a0 + pr[0][col];
        H[(n0 + 1) * F + col] = a1 + pr[1][col];
        H[(n0 + 2) * F + col] = a2 + pr[2][col];
        H[(n0 + 3) * F + col] = a3 + pr[3][col];
    }
}

// ---------------------------------------------------------------------------
// warp scan helpers (float2 componentwise)
__device__ __forceinline__ float2 warp_incl_scan2(float2 v, int lane) {
#pragma unroll
    for (int d = 1; d < 32; d <<= 1) {
        float x = __shfl_up_sync(0xffffffffu, v.x, d);
        float y = __shfl_up_sync(0xffffffffu, v.y, d);
        if (lane >= d) { v.x += x; v.y += y; }
    }
    return v;
}
__device__ __forceinline__ float2 warp_incl_sufscan2(float2 v, int lane) {
#pragma unroll
    for (int d = 1; d < 32; d <<= 1) {
        float x = __shfl_down_sync(0xffffffffu, v.x, d);
        float y = __shfl_down_sync(0xffffffffu, v.y, d);
        if (lane + d < 32) { v.x += x; v.y += y; }
    }
    return v;
}

// ---------------------------------------------------------------------------
// Multi-head (H=128, C=1) GAT attention, sorted-threshold formulation.
// grid (128 heads, 2 dst groups), block 128 threads.
// exp(lrelu(as+ad)) factorizes per branch; the branch is a threshold on as.
// Sort src scores, build exact suffix sums of (P1,P1*v) and exclusive prefix
// sums of (P2,P2*v); each dst = 10-step binary search + 2 lookups.
template <bool CROSS>
__global__ void attn_sorted(const float* __restrict__ H, const float* __restrict__ a_src,
                            const float* __restrict__ a_dst, const float* __restrict__ bias,
                            float* __restrict__ Xout) {
    int h = blockIdx.x;
    int dg = blockIdx.y;
    int sg = CROSS ? (1 - dg) : dg;
    int tid = threadIdx.x;
    int lane = tid & 31, w = tid >> 5;

    __shared__ float sA[512];
    __shared__ float sV[512];
    __shared__ float2 sSuf[513];  // suffix sums of (P1, P1*v)
    __shared__ float2 sPre[513];  // exclusive prefix of (P2, P2*v)
    __shared__ float2 wt1[4], wt2[4];

    float asrc = a_src[h], adst = a_dst[h];
    float bh = bias[h];

    // load src column: a = H*asrc, v = H   (and dst column, issued early)
    float Hd[4];
#pragma unroll
    for (int i = 0; i < 4; i++) {
        int s = tid + i * 128;
        float Hv = H[(sg * 512 + s) * F + h];
        sV[s] = Hv;
        sA[s] = Hv * asrc;
        Hd[i] = H[(dg * 512 + tid + i * 128) * F + h];
    }

    // bitonic sort ascending on sA, payload sV
    for (int k = 2; k <= 512; k <<= 1) {
        for (int j = k >> 1; j > 0; j >>= 1) {
            __syncthreads();
#pragma unroll
            for (int m = 0; m < 4; m++) {
                int i = tid + m * 128;
                int ixj = i ^ j;
                if (ixj > i) {
                    float q0 = sA[i], q1 = sA[ixj];
                    bool up = ((i & k) == 0);
                    if ((q0 > q1) == up) {
                        sA[i] = q1; sA[ixj] = q0;
                        float v0 = sV[i], v1 = sV[ixj];
                        sV[i] = v1; sV[ixj] = v0;
                    }
                }
            }
        }
    }
    __syncthreads();

    float M = sA[511];  // max src score (sorted)

    // per-thread contiguous 4 elements: compute P's + local scans
    float2 tp1[4], lp2[4], lp1[4];
    float2 c2 = make_float2(0.f, 0.f);
#pragma unroll
    for (int e = 0; e < 4; e++) {
        int j = 4 * tid + e;
        float a = sA[j], v = sV[j];
        float q1 = __expf(a - M);
        float q2 = __expf(NSLOPE * (a - M));
        tp1[e] = make_float2(q1, q1 * v);
        c2.x += q2; c2.y += q2 * v;
        lp2[e] = c2;
    }
    float2 c1 = make_float2(0.f, 0.f);
#pragma unroll
    for (int e = 3; e >= 0; e--) {
        c1.x += tp1[e].x; c1.y += tp1[e].y;
        lp1[e] = c1;
    }

    // warp scans
    float2 tincl = warp_incl_scan2(lp2[3], lane);
    float2 texcl;
    texcl.x = __shfl_up_sync(0xffffffffu, tincl.x, 1);
    texcl.y = __shfl_up_sync(0xffffffffu, tincl.y, 1);
    if (lane == 0) texcl = make_float2(0.f, 0.f);
    if (lane == 31) wt2[w] = tincl;

    float2 sincl = warp_incl_sufscan2(lp1[0], lane);
    float2 sexcl;
    sexcl.x = __shfl_down_sync(0xffffffffu, sincl.x, 1);
    sexcl.y = __shfl_down_sync(0xffffffffu, sincl.y, 1);
    if (lane == 31) sexcl = make_float2(0.f, 0.f);
    if (lane == 0) wt1[w] = sincl;
    __syncthreads();

    float2 base2 = texcl, base1 = sexcl;
#pragma unroll
    for (int ww = 0; ww < 4; ww++) {
        if (ww < w) { base2.x += wt2[ww].x; base2.y += wt2[ww].y; }
        if (ww > w) { base1.x += wt1[ww].x; base1.y += wt1[ww].y; }
    }
#pragma unroll
    for (int e = 0; e < 4; e++) {
        int j = 4 * tid + e;
        float2 pre = base2;
        if (e > 0) { pre.x += lp2[e - 1].x; pre.y += lp2[e - 1].y; }
        sPre[j] = pre;
        sSuf[j] = make_float2(base1.x + lp1[e].x, base1.y + lp1[e].y);
    }
    if (tid == 127) sPre[512] = make_float2(base2.x + lp2[3].x, base2.y + lp2[3].y);
    if (tid == 0) sSuf[512] = make_float2(0.f, 0.f);
    __syncthreads();

    // per-dst: binary search rank of threshold t = -ad, then lookups
    float adv[4], t[4];
    int pos[4];
#pragma unroll
    for (int i = 0; i < 4; i++) {
        adv[i] = Hd[i] * adst;
        t[i] = -adv[i];
        pos[i] = 0;
    }
#pragma unroll
    for (int half = 256; half >= 1; half >>= 1) {
#pragma unroll
        for (int i = 0; i < 4; i++)
            if (sA[pos[i] + half - 1] <= t[i]) pos[i] += half;
    }
#pragma unroll
    for (int i = 0; i < 4; i++)
        if (sA[pos[i]] <= t[i]) pos[i]++;  // all-<= case -> 512

#pragma unroll
    for (int i = 0; i < 4; i++) {
        float2 S1 = sSuf[pos[i]];  // sum over srcs with score > 0 branch
        float2 S2 = sPre[pos[i]];  // sum over srcs with score <= 0 branch
        float ad = adv[i];
        float T = M + ad;  // max pre-activation score over group srcs
        float tmax = T, ts = 0.f;
        if (CROSS) {
            ts = Hd[i] * asrc + ad;  // self-loop score
            tmax = fmaxf(tmax, ts);
        }
        float C = lrelu(tmax);
        float f1 = __expf(T - C);
        float f2 = __expf(NSLOPE * T - C);
        float num = f1 * S1.y + f2 * S2.y;
        float den = f1 * S1.x + f2 * S2.x;
        if (CROSS) {
            float ws = __expf(lrelu(ts) - C);
            num = fmaf(ws, Hd[i], num);
            den += ws;
        }
        float o = num / (den + 1e-16f) + bh;
        o = o > 0.f ? o : expm1f(o);  // ELU
        Xout[(dg * 512 + tid + i * 128) * F + h] = o;
    }
}

// ---------------------------------------------------------------------------
// final layer (heads=1, out_ch=128): per-node attention logits
__global__ void dots_kernel(const float* __restrict__ H, const float* __restrict__ a_s,
                            const float* __restrict__ a_d, float* __restrict__ asf,
                            float* __restrict__ adf) {
    int n = blockIdx.x, t = threadIdx.x;
    float h = H[n * F + t];
    float s1 = h * a_s[t];
    float s2 = h * a_d[t];
#pragma unroll
    for (int o = 16; o; o >>= 1) {
        s1 += __shfl_xor_sync(0xffffffffu, s1, o);
        s2 += __shfl_xor_sync(0xffffffffu, s2, o);
    }
    __shared__ float r1[4], r2[4];
    if ((t & 31) == 0) { r1[t >> 5] = s1; r2[t >> 5] = s2; }
    __syncthreads();
    if (t == 0) {
        asf[n] = r1[0] + r1[1] + r1[2] + r1[3];
        adf[n] = r2[0] + r2[1] + r2[2] + r2[3];
    }
}

// final cross-attention: 8 dsts/block, 256 threads (128 cols x 2 s-halves)
__global__ void final_attn(const float* __restrict__ H, const float* __restrict__ asf,
                           const float* __restrict__ adf, const float* __restrict__ bias,
                           float* __restrict__ out) {
    int d0 = blockIdx.x * 8;
    int dg = d0 >> 9;
    int sg = 1 - dg;
    int tid = threadIdx.x;
    int col = tid & 127, sh = tid >> 7;
    int w = tid >> 5, lane = tid & 31;

    __shared__ float sAsf[512];
    __shared__ float4 swq[512][2];  // weights for 8 dsts, packed by 4
    __shared__ float sAdf[8], sM[8], sSelf[8], sDen[8];
    __shared__ float pr[8][128];
    __shared__ float dred[8][256];
    __shared__ float red[8];

    float mloc = -1e30f;
    for (int s = tid; s < 512; s += 256) {
        float v = asf[sg * 512 + s];
        sAsf[s] = v;
        mloc = fmaxf(mloc, v);
    }
#pragma unroll
    for (int o = 16; o; o >>= 1) mloc = fmaxf(mloc, __shfl_xor_sync(0xffffffffu, mloc, o));
    if (lane == 0) red[w] = mloc;
    __syncthreads();
    float maxasf = red[0];
#pragma unroll
    for (int ww = 1; ww < 8; ww++) maxasf = fmaxf(maxasf, red[ww]);

    if (tid < 8) {
        int dn = d0 + tid;
        float ad = adf[dn];
        float ts = asf[dn] + ad;
        float tmax = fmaxf(maxasf + ad, ts);
        float mm = lrelu(tmax);
        sAdf[tid] = ad;
        sM[tid] = mm;
        sSelf[tid] = __expf(lrelu(ts) - mm);
    }
    __syncthreads();

    float dl[8] = {0, 0, 0, 0, 0, 0, 0, 0};
    for (int s = tid; s < 512; s += 256) {
        float a = sAsf[s];
        float wv[8];
#pragma unroll
        for (int d = 0; d < 8; d++) {
            wv[d] = __expf(lrelu(a + sAdf[d]) - sM[d]);
            dl[d] += wv[d];
        }
        swq[s][0] = make_float4(wv[0], wv[1], wv[2], wv[3]);
        swq[s][1] = make_float4(wv[4], wv[5], wv[6], wv[7]);
    }
#pragma unroll
    for (int d = 0; d < 8; d++) dred[d][tid] = dl[d];
    __syncthreads();
    {
        float x = dred[w][lane] + dred[w][lane + 32] + dred[w][lane + 64] + dred[w][lane + 96] +
                  dred[w][lane + 128] + dred[w][lane + 160] + dred[w][lane + 192] + dred[w][lane + 224];
#pragma unroll
        for (int o = 16; o; o >>= 1) x += __shfl_xor_sync(0xffffffffu, x, o);
        if (lane == 0) sDen[w] = x;
    }
    __syncthreads();

    float acc[8] = {0, 0, 0, 0, 0, 0, 0, 0};
    const float* Hs = H + (sg * 512 + sh * 256) * F + col;
#pragma unroll 2
    for (int s = 0; s < 256; s++) {
        float hv = Hs[s * F];
        int ss = sh * 256 + s;
        float4 w0 = swq[ss][0];
        float4 w1 = swq[ss][1];
        acc[0] = fmaf(w0.x, hv, acc[0]);
        acc[1] = fmaf(w0.y, hv, acc[1]);
        acc[2] = fmaf(w0.z, hv, acc[2]);
        acc[3] = fmaf(w0.w, hv, acc[3]);
        acc[4] = fmaf(w1.x, hv, acc[4]);
        acc[5] = fmaf(w1.y, hv, acc[5]);
        acc[6] = fmaf(w1.z, hv, acc[6]);
        acc[7] = fmaf(w1.w, hv, acc[7]);
    }
    if (sh) {
#pragma unroll
        for (int d = 0; d < 8; d++) pr[d][col] = acc[d];
    }
    __syncthreads();
    if (!sh) {
        float bc = bias[col];
#pragma unroll
        for (int d = 0; d < 8; d++) {
            int dn = d0 + d;
            float Hdv = H[dn * F + col];
            float num = acc[d] + pr[d][col] + sSelf[d] * Hdv;
            out[dn * F + col] = num / (sDen[d] + sSelf[d] + 1e-16f) + bc;
        }
    }
}

// ---------------------------------------------------------------------------
extern "C" void kernel_launch(void* const* d_in, const int* in_sizes, int n_in,
                              void* d_out, int out_size) {
    const float* desc1 = (const float*)d_in[0];
    const float* desc2 = (const float*)d_in[1];
    const float* W1 = (const float*)d_in[2];
    const float* as1 = (const float*)d_in[3];
    const float* ad1 = (const float*)d_in[4];
    const float* b1 = (const float*)d_in[5];
    const float* W2 = (const float*)d_in[6];
    const float* as2 = (const float*)d_in[7];
    const float* ad2 = (const float*)d_in[8];
    const float* b2 = (const float*)d_in[9];
    float* out = (float*)d_out;

    float *X, *Y, *H, *asf, *adf;
    cudaGetSymbolAddress((void**)&X, g_X);
    cudaGetSymbolAddress((void**)&Y, g_Y);
    cudaGetSymbolAddress((void**)&H, g_H);
    cudaGetSymbolAddress((void**)&asf, g_asf);
    cudaGetSymbolAddress((void**)&adf, g_adf);

    concat_kernel<<<256, 512>>>(desc1, desc2, X);

    dim3 ag(128, 2);
    // conv1: inside
    gemm4<<<256, 256>>>(X, W1, H);
    attn_sorted<false><<<ag, 128>>>(H, as1, ad1, b1, Y);
    // conv2: cross
    gemm4<<<256, 256>>>(Y, W1, H);
    attn_sorted<true><<<ag, 128>>>(H, as1, ad1, b1, X);
    // conv3: inside
    gemm4<<<256, 256>>>(X, W1, H);
    attn_sorted<false><<<ag, 128>>>(H, as1, ad1, b1, Y);
    // conv4: cross
    gemm4<<<256, 256>>>(Y, W1, H);
    attn_sorted<true><<<ag, 128>>>(H, as1, ad1, b1, X);
    // final conv: cross, heads=1, out_ch=128, no ELU
    gemm4<<<256, 256>>>(X, W2, H);
    dots_kernel<<<1024, 128>>>(H, as2, ad2, asf, adf);
    final_attn<<<128, 256>>>(H, asf, adf, b2, out);
}